// round 11
// baseline (speedup 1.0000x reference)
#include <cuda_runtime.h>
#include <cuda_fp16.h>

#define NN 100000
#define NE 1600000

#define SCAN_B 1024
#define NBLK ((NN + SCAN_B - 1) / SCAN_B)   // 98

// ---- scratch (device globals: no allocation allowed) ----
__device__ float g_deg[NN];
__device__ int   g_cnt[NN];
__device__ int   g_off[NN + 1];
__device__ int   g_bsum[NBLK];
__device__ __align__(16) int    g_rank[NE];     // edge rank within its dst bucket
__device__ __align__(16) int2   g_edge[NE];     // CSR slot: {src, norm bits}
__device__ __align__(16) __half g_h1[NN * 48];
__device__ __align__(16) float  g_acc1[NN * 48];
__device__ __align__(16) __half g_h2[NN * 40];
__device__ __align__(16) float  g_acc2[NN * 40];

__device__ __forceinline__ float neg_inf() { return __int_as_float(0xff800000); }

__global__ void __launch_bounds__(256) zero_init() {
    int i = blockIdx.x * blockDim.x + threadIdx.x;
    if (i < NN) {
        g_deg[i] = 0.f;
        g_cnt[i] = 0;
    }
}

// Weighted in-degree + count histogram; atomic return = stable rank.
__global__ void __launch_bounds__(256)
prep_edges(const int* __restrict__ ei, const float* __restrict__ ew) {
    int t = blockIdx.x * blockDim.x + threadIdx.x;
    int e = t * 4;
    if (e + 4 <= NE) {
        int4   d4 = *reinterpret_cast<const int4*>(ei + NE + e);
        float4 w4 = *reinterpret_cast<const float4*>(ew + e);
        int4 r;
        atomicAdd(&g_deg[d4.x], w4.x); r.x = atomicAdd(&g_cnt[d4.x], 1);
        atomicAdd(&g_deg[d4.y], w4.y); r.y = atomicAdd(&g_cnt[d4.y], 1);
        atomicAdd(&g_deg[d4.z], w4.z); r.z = atomicAdd(&g_cnt[d4.z], 1);
        atomicAdd(&g_deg[d4.w], w4.w); r.w = atomicAdd(&g_cnt[d4.w], 1);
        *reinterpret_cast<int4*>(g_rank + e) = r;
    } else {
        for (int k = e; k < NE; k++) {
            int d = ei[NE + k];
            atomicAdd(&g_deg[d], ew[k]);
            g_rank[k] = atomicAdd(&g_cnt[d], 1);
        }
    }
}

// Scan phase 1 (+ fused dinv): block-local exclusive scan of g_cnt.
__global__ void __launch_bounds__(SCAN_B) scan_phase1() {
    __shared__ int sums[SCAN_B];
    int tid = threadIdx.x;
    int i = blockIdx.x * SCAN_B + tid;
    int v = (i < NN) ? g_cnt[i] : 0;
    sums[tid] = v;
    if (i < NN) {
        float d = g_deg[i];
        g_deg[i] = (d > 0.f) ? rsqrtf(d) : 0.f;
    }
    __syncthreads();
#pragma unroll
    for (int off = 1; off < SCAN_B; off <<= 1) {
        int t = (tid >= off) ? sums[tid - off] : 0;
        __syncthreads();
        sums[tid] += t;
        __syncthreads();
    }
    if (i < NN) g_off[i] = sums[tid] - v;
    if (tid == SCAN_B - 1) g_bsum[blockIdx.x] = sums[tid];
}

// Fused scan phases 2+3: redundant block-sum scan in smem, then add prefix.
__global__ void __launch_bounds__(256) scan_phase23() {
    __shared__ int s[128];
    int tid = threadIdx.x;
    if (tid < 128) s[tid] = (tid < NBLK) ? g_bsum[tid] : 0;
    __syncthreads();
#pragma unroll
    for (int off = 1; off < 128; off <<= 1) {
        int t = (tid < 128 && tid >= off) ? s[tid - off] : 0;
        __syncthreads();
        if (tid < 128) s[tid] += t;
        __syncthreads();
    }
    int i = blockIdx.x * blockDim.x + tid;
    if (i < NN) {
        int bi = i >> 10;
        int add = (bi == 0) ? 0 : s[bi - 1];
        g_off[i] += add;
    }
    if (i == 0) g_off[NN] = NE;
}

// CSR fill: no atomics — position = offset + precomputed rank.
__global__ void __launch_bounds__(256)
fill_csr(const int* __restrict__ ei, const float* __restrict__ ew) {
    int t = blockIdx.x * blockDim.x + threadIdx.x;
    int e = t * 4;
    if (e + 4 <= NE) {
        int4   s4 = *reinterpret_cast<const int4*>(ei + e);
        int4   d4 = *reinterpret_cast<const int4*>(ei + NE + e);
        float4 w4 = *reinterpret_cast<const float4*>(ew + e);
        int4   r4 = *reinterpret_cast<const int4*>(g_rank + e);
        float nx = g_deg[s4.x] * w4.x * g_deg[d4.x];
        float ny = g_deg[s4.y] * w4.y * g_deg[d4.y];
        float nz = g_deg[s4.z] * w4.z * g_deg[d4.z];
        float nw = g_deg[s4.w] * w4.w * g_deg[d4.w];
        g_edge[g_off[d4.x] + r4.x] = make_int2(s4.x, __float_as_int(nx));
        g_edge[g_off[d4.y] + r4.y] = make_int2(s4.y, __float_as_int(ny));
        g_edge[g_off[d4.z] + r4.z] = make_int2(s4.z, __float_as_int(nz));
        g_edge[g_off[d4.w] + r4.w] = make_int2(s4.w, __float_as_int(nw));
    } else {
        for (int k = e; k < NE; k++) {
            int s = ei[k], d = ei[NE + k];
            float nm = g_deg[s] * ew[k] * g_deg[d];
            g_edge[g_off[d] + g_rank[k]] = make_int2(s, __float_as_int(nm));
        }
    }
}

// Dual GEMM (scalar FFMA, ROWS=32 for occupancy): h = act(x)@W (fp16),
// acc = act(x)@V + b (fp32).
template <int FIN, int FOUT, bool RELU>
__global__ void __launch_bounds__(FOUT * 4)
gemm_dual(const float* __restrict__ x, const float* __restrict__ W,
          const float* __restrict__ V, const float* __restrict__ b,
          __half* __restrict__ h, float* __restrict__ acc) {
    constexpr int ROWS = 32;
    constexpr int STR  = FIN + 4;
    constexpr int JR   = ROWS / 4;          // 8 rows per thread
    __shared__ float2 WV[FIN * FOUT];
    __shared__ float  xs[ROWS * STR];

    const int tid = threadIdx.y * FOUT + threadIdx.x;
    const int nth = FOUT * 4;

    for (int i = tid; i < FIN * FOUT; i += nth)
        WV[i] = make_float2(W[i], V[i]);

    const int row0 = blockIdx.x * ROWS;
    for (int i = tid; i < ROWS * FIN; i += nth) {
        int r = i / FIN, c = i - r * FIN;
        int gr = row0 + r;
        float v = (gr < NN) ? x[(size_t)gr * FIN + c] : 0.f;
        if (RELU) v = fmaxf(v, 0.f);
        xs[r * STR + c] = v;
    }
    __syncthreads();

    const int f = threadIdx.x;
    float aW[JR], aV[JR];
#pragma unroll
    for (int j = 0; j < JR; j++) { aW[j] = 0.f; aV[j] = 0.f; }

    for (int k = 0; k < FIN; k += 4) {
        float2 wv0 = WV[(k + 0) * FOUT + f];
        float2 wv1 = WV[(k + 1) * FOUT + f];
        float2 wv2 = WV[(k + 2) * FOUT + f];
        float2 wv3 = WV[(k + 3) * FOUT + f];
#pragma unroll
        for (int j = 0; j < JR; j++) {
            const float4 xv = *reinterpret_cast<const float4*>(
                &xs[(threadIdx.y + j * 4) * STR + k]);
            aW[j] = fmaf(xv.x, wv0.x, aW[j]); aV[j] = fmaf(xv.x, wv0.y, aV[j]);
            aW[j] = fmaf(xv.y, wv1.x, aW[j]); aV[j] = fmaf(xv.y, wv1.y, aV[j]);
            aW[j] = fmaf(xv.z, wv2.x, aW[j]); aV[j] = fmaf(xv.z, wv2.y, aV[j]);
            aW[j] = fmaf(xv.w, wv3.x, aW[j]); aV[j] = fmaf(xv.w, wv3.y, aV[j]);
        }
    }

    const float bf = b[f];
#pragma unroll
    for (int j = 0; j < JR; j++) {
        int gr = row0 + threadIdx.y + j * 4;
        if (gr < NN) {
            h[(size_t)gr * FOUT + f]   = __float2half_rn(aW[j]);
            acc[(size_t)gr * FOUT + f] = aV[j] + bf;
        }
    }
}

// CSR aggregation: one warp per node; coalesced edge-record loads +
// shuffle-broadcast; half2 gathers with 8 rows in flight; optional fused LSM.
template <int FOUT, bool LSM>
__global__ void __launch_bounds__(256)
agg_csr(const __half* __restrict__ h, const float* __restrict__ accin,
        float* __restrict__ out) {
    constexpr int HL = FOUT / 2;
    int gw = (blockIdx.x * blockDim.x + threadIdx.x) >> 5;
    if (gw >= NN) return;
    int lane = threadIdx.x & 31;
    bool act = lane < HL;

    int e0 = g_off[gw];
    int e1 = g_off[gw + 1];

    const __half2* h2p = reinterpret_cast<const __half2*>(h);

    float2 a = make_float2(0.f, 0.f);
    if (act) a = reinterpret_cast<const float2*>(accin + (size_t)gw * FOUT)[lane];

    for (int base = e0; base < e1; base += 32) {
        int idx = base + lane;
        int2 rec = (idx < e1) ? g_edge[idx] : make_int2(0, 0);
        int cnt = min(32, e1 - base);
        int j = 0;
        for (; j + 8 <= cnt; j += 8) {
            int   s[8];
            float n[8];
            float2 v[8];
#pragma unroll
            for (int q = 0; q < 8; q++) {
                s[q] = __shfl_sync(0xffffffffu, rec.x, j + q);
                n[q] = __int_as_float(__shfl_sync(0xffffffffu, rec.y, j + q));
            }
#pragma unroll
            for (int q = 0; q < 8; q++)
                v[q] = act ? __half22float2(h2p[(size_t)s[q] * HL + lane])
                           : make_float2(0.f, 0.f);
#pragma unroll
            for (int q = 0; q < 8; q++) {
                a.x = fmaf(v[q].x, n[q], a.x);
                a.y = fmaf(v[q].y, n[q], a.y);
            }
        }
        for (; j < cnt; j++) {
            int   s  = __shfl_sync(0xffffffffu, rec.x, j);
            float nm = __int_as_float(__shfl_sync(0xffffffffu, rec.y, j));
            float2 v = make_float2(0.f, 0.f);
            if (act) v = __half22float2(h2p[(size_t)s * HL + lane]);
            a.x = fmaf(v.x, nm, a.x);
            a.y = fmaf(v.y, nm, a.y);
        }
    }

    if (!LSM) {
        if (act) reinterpret_cast<float2*>(out + (size_t)gw * FOUT)[lane] = a;
    } else {
        float vx = act ? fmaxf(a.x, 0.f) : neg_inf();
        float vy = act ? fmaxf(a.y, 0.f) : neg_inf();
        float m = fmaxf(vx, vy);
#pragma unroll
        for (int o = 16; o; o >>= 1) m = fmaxf(m, __shfl_xor_sync(0xffffffffu, m, o));
        float sv = act ? (__expf(vx - m) + __expf(vy - m)) : 0.f;
#pragma unroll
        for (int o = 16; o; o >>= 1) sv += __shfl_xor_sync(0xffffffffu, sv, o);
        float lse = m + __logf(sv);
        if (act)
            reinterpret_cast<float2*>(out + (size_t)gw * FOUT)[lane] =
                make_float2(vx - lse, vy - lse);
    }
}

extern "C" void kernel_launch(void* const* d_in, const int* in_sizes, int n_in,
                              void* d_out, int out_size) {
    const float* x  = (const float*)d_in[0];
    const int*   ei = (const int*)d_in[1];
    const float* ew = (const float*)d_in[2];
    const float* W1 = (const float*)d_in[3];
    const float* V1 = (const float*)d_in[4];
    const float* b1 = (const float*)d_in[5];
    const float* W2 = (const float*)d_in[6];
    const float* V2 = (const float*)d_in[7];
    const float* b2 = (const float*)d_in[8];
    float* out = (float*)d_out;

    void *h1p, *acc1p, *h2p, *acc2p;
    cudaGetSymbolAddress(&h1p,   g_h1);
    cudaGetSymbolAddress(&acc1p, g_acc1);
    cudaGetSymbolAddress(&h2p,   g_h2);
    cudaGetSymbolAddress(&acc2p, g_acc2);

    cudaStream_t s2;
    cudaStreamCreateWithFlags(&s2, cudaStreamNonBlocking);
    cudaEvent_t evF, evJ;
    cudaEventCreateWithFlags(&evF, cudaEventDisableTiming);
    cudaEventCreateWithFlags(&evJ, cudaEventDisableTiming);

    cudaEventRecord(evF, 0);
    cudaStreamWaitEvent(s2, evF, 0);

    zero_init   <<<(NN + 255) / 256, 256>>>();                         // 1
    prep_edges  <<<(NE / 4 + 255) / 256, 256>>>(ei, ew);               // 2
    scan_phase1 <<<NBLK, SCAN_B>>>();                                  // 3 (+dinv)
    gemm_dual<64, 48, false><<<(NN + 31) / 32, dim3(48, 4), 0, s2>>>(  // 4 (profiled)
        x, W1, V1, b1, (__half*)h1p, (float*)acc1p);
    cudaEventRecord(evJ, s2);
    scan_phase23<<<(NN + 255) / 256, 256>>>();                         // 5
    fill_csr    <<<(NE / 4 + 255) / 256, 256>>>(ei, ew);               // 6

    cudaStreamWaitEvent(0, evJ, 0);

    agg_csr<48, false><<<(NN * 32 + 255) / 256, 256>>>(                // 7
        (const __half*)h1p, (const float*)acc1p, (float*)acc1p);

    gemm_dual<48, 40, true><<<(NN + 31) / 32, dim3(40, 4)>>>(          // 8
        (const float*)acc1p, W2, V2, b2, (__half*)h2p, (float*)acc2p);

    agg_csr<40, true><<<(NN * 32 + 255) / 256, 256>>>(                 // 9
        (const __half*)h2p, (const float*)acc2p, out);
}

// round 12
// speedup vs baseline: 1.1016x; 1.1016x over previous
#include <cuda_runtime.h>
#include <cuda_fp16.h>

#define NN 100000
#define NE 1600000

#define SCAN_B 1024
#define NBLK ((NN + SCAN_B - 1) / SCAN_B)   // 98

// ---- scratch (device globals: no allocation allowed) ----
__device__ float g_deg[NN];
__device__ int   g_cnt[NN];
__device__ int   g_off[NN + 1];
__device__ int   g_bsum[NBLK];
__device__ __align__(16) int    g_rank[NE];     // edge rank within its dst bucket
__device__ __align__(16) int2   g_edge[NE];     // CSR slot: {src, norm bits}
__device__ __align__(16) __half g_h1[NN * 48];
__device__ __align__(16) float  g_acc1[NN * 48];
__device__ __align__(16) __half g_h2[NN * 40];
__device__ __align__(16) float  g_acc2[NN * 40];

__device__ __forceinline__ float neg_inf() { return __int_as_float(0xff800000); }

__global__ void __launch_bounds__(256) zero_init() {
    int i = blockIdx.x * blockDim.x + threadIdx.x;
    if (i < NN) {
        g_deg[i] = 0.f;
        g_cnt[i] = 0;
    }
}

// Weighted in-degree + count histogram; atomic return = stable rank.
__global__ void __launch_bounds__(256)
prep_edges(const int* __restrict__ ei, const float* __restrict__ ew) {
    int t = blockIdx.x * blockDim.x + threadIdx.x;
    int e = t * 4;
    if (e + 4 <= NE) {
        int4   d4 = *reinterpret_cast<const int4*>(ei + NE + e);
        float4 w4 = *reinterpret_cast<const float4*>(ew + e);
        int4 r;
        atomicAdd(&g_deg[d4.x], w4.x); r.x = atomicAdd(&g_cnt[d4.x], 1);
        atomicAdd(&g_deg[d4.y], w4.y); r.y = atomicAdd(&g_cnt[d4.y], 1);
        atomicAdd(&g_deg[d4.z], w4.z); r.z = atomicAdd(&g_cnt[d4.z], 1);
        atomicAdd(&g_deg[d4.w], w4.w); r.w = atomicAdd(&g_cnt[d4.w], 1);
        *reinterpret_cast<int4*>(g_rank + e) = r;
    } else {
        for (int k = e; k < NE; k++) {
            int d = ei[NE + k];
            atomicAdd(&g_deg[d], ew[k]);
            g_rank[k] = atomicAdd(&g_cnt[d], 1);
        }
    }
}

// Scan phase 1 (+ fused dinv): block-local exclusive scan of g_cnt.
__global__ void __launch_bounds__(SCAN_B) scan_phase1() {
    __shared__ int sums[SCAN_B];
    int tid = threadIdx.x;
    int i = blockIdx.x * SCAN_B + tid;
    int v = (i < NN) ? g_cnt[i] : 0;
    sums[tid] = v;
    if (i < NN) {
        float d = g_deg[i];
        g_deg[i] = (d > 0.f) ? rsqrtf(d) : 0.f;
    }
    __syncthreads();
#pragma unroll
    for (int off = 1; off < SCAN_B; off <<= 1) {
        int t = (tid >= off) ? sums[tid - off] : 0;
        __syncthreads();
        sums[tid] += t;
        __syncthreads();
    }
    if (i < NN) g_off[i] = sums[tid] - v;
    if (tid == SCAN_B - 1) g_bsum[blockIdx.x] = sums[tid];
}

// Fused scan phases 2+3: redundant block-sum scan in smem, then add prefix.
__global__ void __launch_bounds__(256) scan_phase23() {
    __shared__ int s[128];
    int tid = threadIdx.x;
    if (tid < 128) s[tid] = (tid < NBLK) ? g_bsum[tid] : 0;
    __syncthreads();
#pragma unroll
    for (int off = 1; off < 128; off <<= 1) {
        int t = (tid < 128 && tid >= off) ? s[tid - off] : 0;
        __syncthreads();
        if (tid < 128) s[tid] += t;
        __syncthreads();
    }
    int i = blockIdx.x * blockDim.x + tid;
    if (i < NN) {
        int bi = i >> 10;
        int add = (bi == 0) ? 0 : s[bi - 1];
        g_off[i] += add;
    }
    if (i == 0) g_off[NN] = NE;
}

// CSR fill: no atomics — position = offset + precomputed rank.
__global__ void __launch_bounds__(256)
fill_csr(const int* __restrict__ ei, const float* __restrict__ ew) {
    int t = blockIdx.x * blockDim.x + threadIdx.x;
    int e = t * 4;
    if (e + 4 <= NE) {
        int4   s4 = *reinterpret_cast<const int4*>(ei + e);
        int4   d4 = *reinterpret_cast<const int4*>(ei + NE + e);
        float4 w4 = *reinterpret_cast<const float4*>(ew + e);
        int4   r4 = *reinterpret_cast<const int4*>(g_rank + e);
        float nx = g_deg[s4.x] * w4.x * g_deg[d4.x];
        float ny = g_deg[s4.y] * w4.y * g_deg[d4.y];
        float nz = g_deg[s4.z] * w4.z * g_deg[d4.z];
        float nw = g_deg[s4.w] * w4.w * g_deg[d4.w];
        g_edge[g_off[d4.x] + r4.x] = make_int2(s4.x, __float_as_int(nx));
        g_edge[g_off[d4.y] + r4.y] = make_int2(s4.y, __float_as_int(ny));
        g_edge[g_off[d4.z] + r4.z] = make_int2(s4.z, __float_as_int(nz));
        g_edge[g_off[d4.w] + r4.w] = make_int2(s4.w, __float_as_int(nw));
    } else {
        for (int k = e; k < NE; k++) {
            int s = ei[k], d = ei[NE + k];
            float nm = g_deg[s] * ew[k] * g_deg[d];
            g_edge[g_off[d] + g_rank[k]] = make_int2(s, __float_as_int(nm));
        }
    }
}

// Dual GEMM (scalar FFMA, ROWS=64, 5 blocks/SM forced): h = act(x)@W (fp16),
// acc = act(x)@V + b (fp32).
template <int FIN, int FOUT, bool RELU>
__global__ void __launch_bounds__(FOUT * 4, 5)
gemm_dual(const float* __restrict__ x, const float* __restrict__ W,
          const float* __restrict__ V, const float* __restrict__ b,
          __half* __restrict__ h, float* __restrict__ acc) {
    constexpr int ROWS = 64;
    constexpr int STR  = FIN + 4;
    constexpr int JR   = ROWS / 4;
    __shared__ float2 WV[FIN * FOUT];
    __shared__ float  xs[ROWS * STR];

    const int tid = threadIdx.y * FOUT + threadIdx.x;
    const int nth = FOUT * 4;

    for (int i = tid; i < FIN * FOUT; i += nth)
        WV[i] = make_float2(W[i], V[i]);

    const int row0 = blockIdx.x * ROWS;
    for (int i = tid; i < ROWS * FIN; i += nth) {
        int r = i / FIN, c = i - r * FIN;
        int gr = row0 + r;
        float v = (gr < NN) ? x[(size_t)gr * FIN + c] : 0.f;
        if (RELU) v = fmaxf(v, 0.f);
        xs[r * STR + c] = v;
    }
    __syncthreads();

    const int f = threadIdx.x;
    float aW[JR], aV[JR];
#pragma unroll
    for (int j = 0; j < JR; j++) { aW[j] = 0.f; aV[j] = 0.f; }

    for (int k = 0; k < FIN; k += 4) {
        float2 wv0 = WV[(k + 0) * FOUT + f];
        float2 wv1 = WV[(k + 1) * FOUT + f];
        float2 wv2 = WV[(k + 2) * FOUT + f];
        float2 wv3 = WV[(k + 3) * FOUT + f];
#pragma unroll
        for (int j = 0; j < JR; j++) {
            const float4 xv = *reinterpret_cast<const float4*>(
                &xs[(threadIdx.y + j * 4) * STR + k]);
            aW[j] = fmaf(xv.x, wv0.x, aW[j]); aV[j] = fmaf(xv.x, wv0.y, aV[j]);
            aW[j] = fmaf(xv.y, wv1.x, aW[j]); aV[j] = fmaf(xv.y, wv1.y, aV[j]);
            aW[j] = fmaf(xv.z, wv2.x, aW[j]); aV[j] = fmaf(xv.z, wv2.y, aV[j]);
            aW[j] = fmaf(xv.w, wv3.x, aW[j]); aV[j] = fmaf(xv.w, wv3.y, aV[j]);
        }
    }

    const float bf = b[f];
#pragma unroll
    for (int j = 0; j < JR; j++) {
        int gr = row0 + threadIdx.y + j * 4;
        if (gr < NN) {
            h[(size_t)gr * FOUT + f]   = __float2half_rn(aW[j]);
            acc[(size_t)gr * FOUT + f] = aV[j] + bf;
        }
    }
}

// CSR aggregation: one warp per node; coalesced edge-record loads +
// shuffle-broadcast; half2 gathers, 4 rows in flight; optional fused LSM.
template <int FOUT, bool LSM>
__global__ void __launch_bounds__(256)
agg_csr(const __half* __restrict__ h, const float* __restrict__ accin,
        float* __restrict__ out) {
    constexpr int HL = FOUT / 2;
    int gw = (blockIdx.x * blockDim.x + threadIdx.x) >> 5;
    if (gw >= NN) return;
    int lane = threadIdx.x & 31;
    bool act = lane < HL;

    int e0 = g_off[gw];
    int e1 = g_off[gw + 1];

    const __half2* h2p = reinterpret_cast<const __half2*>(h);

    float2 a = make_float2(0.f, 0.f);
    if (act) a = reinterpret_cast<const float2*>(accin + (size_t)gw * FOUT)[lane];

    for (int base = e0; base < e1; base += 32) {
        int idx = base + lane;
        int2 rec = (idx < e1) ? g_edge[idx] : make_int2(0, 0);
        int cnt = min(32, e1 - base);
        int j = 0;
        for (; j + 4 <= cnt; j += 4) {
            int s0 = __shfl_sync(0xffffffffu, rec.x, j);
            int s1 = __shfl_sync(0xffffffffu, rec.x, j + 1);
            int s2 = __shfl_sync(0xffffffffu, rec.x, j + 2);
            int s3 = __shfl_sync(0xffffffffu, rec.x, j + 3);
            float n0 = __int_as_float(__shfl_sync(0xffffffffu, rec.y, j));
            float n1 = __int_as_float(__shfl_sync(0xffffffffu, rec.y, j + 1));
            float n2 = __int_as_float(__shfl_sync(0xffffffffu, rec.y, j + 2));
            float n3 = __int_as_float(__shfl_sync(0xffffffffu, rec.y, j + 3));
            float2 v0 = make_float2(0.f, 0.f), v1 = v0, v2 = v0, v3 = v0;
            if (act) {
                v0 = __half22float2(h2p[(size_t)s0 * HL + lane]);
                v1 = __half22float2(h2p[(size_t)s1 * HL + lane]);
                v2 = __half22float2(h2p[(size_t)s2 * HL + lane]);
                v3 = __half22float2(h2p[(size_t)s3 * HL + lane]);
            }
            a.x = fmaf(v0.x, n0, a.x); a.y = fmaf(v0.y, n0, a.y);
            a.x = fmaf(v1.x, n1, a.x); a.y = fmaf(v1.y, n1, a.y);
            a.x = fmaf(v2.x, n2, a.x); a.y = fmaf(v2.y, n2, a.y);
            a.x = fmaf(v3.x, n3, a.x); a.y = fmaf(v3.y, n3, a.y);
        }
        for (; j < cnt; j++) {
            int   s  = __shfl_sync(0xffffffffu, rec.x, j);
            float nm = __int_as_float(__shfl_sync(0xffffffffu, rec.y, j));
            float2 v = make_float2(0.f, 0.f);
            if (act) v = __half22float2(h2p[(size_t)s * HL + lane]);
            a.x = fmaf(v.x, nm, a.x);
            a.y = fmaf(v.y, nm, a.y);
        }
    }

    if (!LSM) {
        if (act) reinterpret_cast<float2*>(out + (size_t)gw * FOUT)[lane] = a;
    } else {
        float vx = act ? fmaxf(a.x, 0.f) : neg_inf();
        float vy = act ? fmaxf(a.y, 0.f) : neg_inf();
        float m = fmaxf(vx, vy);
#pragma unroll
        for (int o = 16; o; o >>= 1) m = fmaxf(m, __shfl_xor_sync(0xffffffffu, m, o));
        float sv = act ? (__expf(vx - m) + __expf(vy - m)) : 0.f;
#pragma unroll
        for (int o = 16; o; o >>= 1) sv += __shfl_xor_sync(0xffffffffu, sv, o);
        float lse = m + __logf(sv);
        if (act)
            reinterpret_cast<float2*>(out + (size_t)gw * FOUT)[lane] =
                make_float2(vx - lse, vy - lse);
    }
}

extern "C" void kernel_launch(void* const* d_in, const int* in_sizes, int n_in,
                              void* d_out, int out_size) {
    const float* x  = (const float*)d_in[0];
    const int*   ei = (const int*)d_in[1];
    const float* ew = (const float*)d_in[2];
    const float* W1 = (const float*)d_in[3];
    const float* V1 = (const float*)d_in[4];
    const float* b1 = (const float*)d_in[5];
    const float* W2 = (const float*)d_in[6];
    const float* V2 = (const float*)d_in[7];
    const float* b2 = (const float*)d_in[8];
    float* out = (float*)d_out;

    void *h1p, *acc1p, *h2p, *acc2p;
    cudaGetSymbolAddress(&h1p,   g_h1);
    cudaGetSymbolAddress(&acc1p, g_acc1);
    cudaGetSymbolAddress(&h2p,   g_h2);
    cudaGetSymbolAddress(&acc2p, g_acc2);

    cudaStream_t s2;
    cudaStreamCreateWithFlags(&s2, cudaStreamNonBlocking);
    cudaEvent_t evF, evJ;
    cudaEventCreateWithFlags(&evF, cudaEventDisableTiming);
    cudaEventCreateWithFlags(&evJ, cudaEventDisableTiming);

    cudaEventRecord(evF, 0);
    cudaStreamWaitEvent(s2, evF, 0);

    zero_init   <<<(NN + 255) / 256, 256>>>();                         // 1
    prep_edges  <<<(NE / 4 + 255) / 256, 256>>>(ei, ew);               // 2
    scan_phase1 <<<NBLK, SCAN_B>>>();                                  // 3 (+dinv)
    gemm_dual<64, 48, false><<<(NN + 63) / 64, dim3(48, 4), 0, s2>>>(  // 4 (profiled)
        x, W1, V1, b1, (__half*)h1p, (float*)acc1p);
    cudaEventRecord(evJ, s2);
    scan_phase23<<<(NN + 255) / 256, 256>>>();                         // 5
    fill_csr    <<<(NE / 4 + 255) / 256, 256>>>(ei, ew);               // 6

    cudaStreamWaitEvent(0, evJ, 0);

    agg_csr<48, false><<<(NN * 32 + 255) / 256, 256>>>(                // 7
        (const __half*)h1p, (const float*)acc1p, (float*)acc1p);

    gemm_dual<48, 40, true><<<(NN + 63) / 64, dim3(40, 4)>>>(          // 8
        (const float*)acc1p, W2, V2, b2, (__half*)h2p, (float*)acc2p);

    agg_csr<40, true><<<(NN * 32 + 255) / 256, 256>>>(                 // 9
        (const __half*)h2p, (const float*)acc2p, out);
}

// round 13
// speedup vs baseline: 1.2008x; 1.0901x over previous
#include <cuda_runtime.h>
#include <cuda_fp16.h>

#define NN 100000
#define NE 1600000

#define SCAN_B 1024
#define NBLK ((NN + SCAN_B - 1) / SCAN_B)   // 98

// ---- scratch (device globals: no allocation allowed) ----
__device__ float g_deg[NN];
__device__ int   g_cnt[NN];
__device__ int   g_cur[NN];
__device__ int   g_off[NN + 1];
__device__ int   g_bsum[NBLK];
__device__ __align__(16) int2   g_edge[NE];     // CSR slot: {src, norm bits}
__device__ __align__(16) __half g_h1[NN * 48];
__device__ __align__(16) float  g_acc1[NN * 48];
__device__ __align__(16) __half g_h2[NN * 40];
__device__ __align__(16) float  g_acc2[NN * 40];

__device__ __forceinline__ float neg_inf() { return __int_as_float(0xff800000); }

__global__ void __launch_bounds__(256) zero_init() {
    int i = blockIdx.x * blockDim.x + threadIdx.x;
    if (i < NN) {
        g_deg[i] = 0.f;
        g_cnt[i] = 0;
        g_cur[i] = 0;
    }
}

// Weighted in-degree + count histogram (fire-and-forget REDG atomics).
__global__ void __launch_bounds__(256)
prep_edges(const int* __restrict__ ei, const float* __restrict__ ew) {
    int t = blockIdx.x * blockDim.x + threadIdx.x;
    int e = t * 4;
    if (e + 4 <= NE) {
        int4   d4 = *reinterpret_cast<const int4*>(ei + NE + e);
        float4 w4 = *reinterpret_cast<const float4*>(ew + e);
        atomicAdd(&g_deg[d4.x], w4.x); atomicAdd(&g_cnt[d4.x], 1);
        atomicAdd(&g_deg[d4.y], w4.y); atomicAdd(&g_cnt[d4.y], 1);
        atomicAdd(&g_deg[d4.z], w4.z); atomicAdd(&g_cnt[d4.z], 1);
        atomicAdd(&g_deg[d4.w], w4.w); atomicAdd(&g_cnt[d4.w], 1);
    } else {
        for (int k = e; k < NE; k++) {
            int d = ei[NE + k];
            atomicAdd(&g_deg[d], ew[k]);
            atomicAdd(&g_cnt[d], 1);
        }
    }
}

// Scan phase 1 (+ fused dinv): block-local exclusive scan of g_cnt.
__global__ void __launch_bounds__(SCAN_B) scan_phase1() {
    __shared__ int sums[SCAN_B];
    int tid = threadIdx.x;
    int i = blockIdx.x * SCAN_B + tid;
    int v = (i < NN) ? g_cnt[i] : 0;
    sums[tid] = v;
    if (i < NN) {
        float d = g_deg[i];
        g_deg[i] = (d > 0.f) ? rsqrtf(d) : 0.f;
    }
    __syncthreads();
#pragma unroll
    for (int off = 1; off < SCAN_B; off <<= 1) {
        int t = (tid >= off) ? sums[tid - off] : 0;
        __syncthreads();
        sums[tid] += t;
        __syncthreads();
    }
    if (i < NN) g_off[i] = sums[tid] - v;
    if (tid == SCAN_B - 1) g_bsum[blockIdx.x] = sums[tid];
}

__global__ void __launch_bounds__(128) scan_phase2() {
    __shared__ int sums[128];
    int tid = threadIdx.x;
    int v = (tid < NBLK) ? g_bsum[tid] : 0;
    sums[tid] = v;
    __syncthreads();
#pragma unroll
    for (int off = 1; off < 128; off <<= 1) {
        int t = (tid >= off) ? sums[tid - off] : 0;
        __syncthreads();
        sums[tid] += t;
        __syncthreads();
    }
    if (tid < NBLK) g_bsum[tid] = sums[tid] - v;   // in-place exclusive prefixes
}

__global__ void __launch_bounds__(256) scan_phase3() {
    int i = blockIdx.x * blockDim.x + threadIdx.x;
    if (i < NN) g_off[i] += g_bsum[i >> 10];
    if (i == 0) g_off[NN] = NE;
}

// CSR fill with atomic cursor (fastest measured variant).
__global__ void __launch_bounds__(256)
fill_csr(const int* __restrict__ ei, const float* __restrict__ ew) {
    int e = blockIdx.x * blockDim.x + threadIdx.x;
    if (e >= NE) return;
    int s = ei[e];
    int d = ei[NE + e];
    float nm = g_deg[s] * ew[e] * g_deg[d];
    int pos = g_off[d] + atomicAdd(&g_cur[d], 1);
    g_edge[pos] = make_int2(s, __float_as_int(nm));
}

// Dual GEMM: ROWS=64, (FOUT x 8) threads, 8 rows per thread.
// h = act(x)@W (fp16) ; acc = act(x)@V + b (fp32).
template <int FIN, int FOUT, bool RELU>
__global__ void __launch_bounds__(FOUT * 8)
gemm_dual(const float* __restrict__ x, const float* __restrict__ W,
          const float* __restrict__ V, const float* __restrict__ b,
          __half* __restrict__ h, float* __restrict__ acc) {
    constexpr int ROWS = 64;
    constexpr int STR  = FIN + 4;
    constexpr int JR   = ROWS / 8;          // 8 rows per thread
    __shared__ float2 WV[FIN * FOUT];
    __shared__ float  xs[ROWS * STR];

    const int tid = threadIdx.y * FOUT + threadIdx.x;
    const int nth = FOUT * 8;

    for (int i = tid; i < FIN * FOUT; i += nth)
        WV[i] = make_float2(W[i], V[i]);

    const int row0 = blockIdx.x * ROWS;
    for (int i = tid; i < ROWS * FIN; i += nth) {
        int r = i / FIN, c = i - r * FIN;
        int gr = row0 + r;
        float v = (gr < NN) ? x[(size_t)gr * FIN + c] : 0.f;
        if (RELU) v = fmaxf(v, 0.f);
        xs[r * STR + c] = v;
    }
    __syncthreads();

    const int f = threadIdx.x;
    float aW[JR], aV[JR];
#pragma unroll
    for (int j = 0; j < JR; j++) { aW[j] = 0.f; aV[j] = 0.f; }

    for (int k = 0; k < FIN; k += 4) {
        float2 wv0 = WV[(k + 0) * FOUT + f];
        float2 wv1 = WV[(k + 1) * FOUT + f];
        float2 wv2 = WV[(k + 2) * FOUT + f];
        float2 wv3 = WV[(k + 3) * FOUT + f];
#pragma unroll
        for (int j = 0; j < JR; j++) {
            const float4 xv = *reinterpret_cast<const float4*>(
                &xs[(threadIdx.y + j * 8) * STR + k]);
            aW[j] = fmaf(xv.x, wv0.x, aW[j]); aV[j] = fmaf(xv.x, wv0.y, aV[j]);
            aW[j] = fmaf(xv.y, wv1.x, aW[j]); aV[j] = fmaf(xv.y, wv1.y, aV[j]);
            aW[j] = fmaf(xv.z, wv2.x, aW[j]); aV[j] = fmaf(xv.z, wv2.y, aV[j]);
            aW[j] = fmaf(xv.w, wv3.x, aW[j]); aV[j] = fmaf(xv.w, wv3.y, aV[j]);
        }
    }

    const float bf = b[f];
#pragma unroll
    for (int j = 0; j < JR; j++) {
        int gr = row0 + threadIdx.y + j * 8;
        if (gr < NN) {
            h[(size_t)gr * FOUT + f]   = __float2half_rn(aW[j]);
            acc[(size_t)gr * FOUT + f] = aV[j] + bf;
        }
    }
}

// CSR aggregation: one warp per node; coalesced edge-record loads +
// shuffle-broadcast; half2 gathers, 4 rows in flight; optional fused LSM.
template <int FOUT, bool LSM>
__global__ void __launch_bounds__(256)
agg_csr(const __half* __restrict__ h, const float* __restrict__ accin,
        float* __restrict__ out) {
    constexpr int HL = FOUT / 2;
    int gw = (blockIdx.x * blockDim.x + threadIdx.x) >> 5;
    if (gw >= NN) return;
    int lane = threadIdx.x & 31;
    bool act = lane < HL;

    int e0 = g_off[gw];
    int e1 = g_off[gw + 1];

    const __half2* h2p = reinterpret_cast<const __half2*>(h);

    float2 a = make_float2(0.f, 0.f);
    if (act) a = reinterpret_cast<const float2*>(accin + (size_t)gw * FOUT)[lane];

    for (int base = e0; base < e1; base += 32) {
        int idx = base + lane;
        int2 rec = (idx < e1) ? g_edge[idx] : make_int2(0, 0);
        int cnt = min(32, e1 - base);
        int j = 0;
        for (; j + 4 <= cnt; j += 4) {
            int s0 = __shfl_sync(0xffffffffu, rec.x, j);
            int s1 = __shfl_sync(0xffffffffu, rec.x, j + 1);
            int s2 = __shfl_sync(0xffffffffu, rec.x, j + 2);
            int s3 = __shfl_sync(0xffffffffu, rec.x, j + 3);
            float n0 = __int_as_float(__shfl_sync(0xffffffffu, rec.y, j));
            float n1 = __int_as_float(__shfl_sync(0xffffffffu, rec.y, j + 1));
            float n2 = __int_as_float(__shfl_sync(0xffffffffu, rec.y, j + 2));
            float n3 = __int_as_float(__shfl_sync(0xffffffffu, rec.y, j + 3));
            float2 v0 = make_float2(0.f, 0.f), v1 = v0, v2 = v0, v3 = v0;
            if (act) {
                v0 = __half22float2(h2p[(size_t)s0 * HL + lane]);
                v1 = __half22float2(h2p[(size_t)s1 * HL + lane]);
                v2 = __half22float2(h2p[(size_t)s2 * HL + lane]);
                v3 = __half22float2(h2p[(size_t)s3 * HL + lane]);
            }
            a.x = fmaf(v0.x, n0, a.x); a.y = fmaf(v0.y, n0, a.y);
            a.x = fmaf(v1.x, n1, a.x); a.y = fmaf(v1.y, n1, a.y);
            a.x = fmaf(v2.x, n2, a.x); a.y = fmaf(v2.y, n2, a.y);
            a.x = fmaf(v3.x, n3, a.x); a.y = fmaf(v3.y, n3, a.y);
        }
        for (; j < cnt; j++) {
            int   s  = __shfl_sync(0xffffffffu, rec.x, j);
            float nm = __int_as_float(__shfl_sync(0xffffffffu, rec.y, j));
            float2 v = make_float2(0.f, 0.f);
            if (act) v = __half22float2(h2p[(size_t)s * HL + lane]);
            a.x = fmaf(v.x, nm, a.x);
            a.y = fmaf(v.y, nm, a.y);
        }
    }

    if (!LSM) {
        if (act) reinterpret_cast<float2*>(out + (size_t)gw * FOUT)[lane] = a;
    } else {
        float vx = act ? fmaxf(a.x, 0.f) : neg_inf();
        float vy = act ? fmaxf(a.y, 0.f) : neg_inf();
        float m = fmaxf(vx, vy);
#pragma unroll
        for (int o = 16; o; o >>= 1) m = fmaxf(m, __shfl_xor_sync(0xffffffffu, m, o));
        float sv = act ? (__expf(vx - m) + __expf(vy - m)) : 0.f;
#pragma unroll
        for (int o = 16; o; o >>= 1) sv += __shfl_xor_sync(0xffffffffu, sv, o);
        float lse = m + __logf(sv);
        if (act)
            reinterpret_cast<float2*>(out + (size_t)gw * FOUT)[lane] =
                make_float2(vx - lse, vy - lse);
    }
}

extern "C" void kernel_launch(void* const* d_in, const int* in_sizes, int n_in,
                              void* d_out, int out_size) {
    const float* x  = (const float*)d_in[0];
    const int*   ei = (const int*)d_in[1];
    const float* ew = (const float*)d_in[2];
    const float* W1 = (const float*)d_in[3];
    const float* V1 = (const float*)d_in[4];
    const float* b1 = (const float*)d_in[5];
    const float* W2 = (const float*)d_in[6];
    const float* V2 = (const float*)d_in[7];
    const float* b2 = (const float*)d_in[8];
    float* out = (float*)d_out;

    void *h1p, *acc1p, *h2p, *acc2p;
    cudaGetSymbolAddress(&h1p,   g_h1);
    cudaGetSymbolAddress(&acc1p, g_acc1);
    cudaGetSymbolAddress(&h2p,   g_h2);
    cudaGetSymbolAddress(&acc2p, g_acc2);

    cudaStream_t s2;
    cudaStreamCreateWithFlags(&s2, cudaStreamNonBlocking);
    cudaEvent_t evF, evJ;
    cudaEventCreateWithFlags(&evF, cudaEventDisableTiming);
    cudaEventCreateWithFlags(&evJ, cudaEventDisableTiming);

    cudaEventRecord(evF, 0);
    cudaStreamWaitEvent(s2, evF, 0);

    zero_init   <<<(NN + 255) / 256, 256>>>();                         // 1
    prep_edges  <<<(NE / 4 + 255) / 256, 256>>>(ei, ew);               // 2
    scan_phase1 <<<NBLK, SCAN_B>>>();                                  // 3 (+dinv)
    gemm_dual<64, 48, false><<<(NN + 63) / 64, dim3(48, 8), 0, s2>>>(  // 4 (profiled)
        x, W1, V1, b1, (__half*)h1p, (float*)acc1p);
    cudaEventRecord(evJ, s2);
    scan_phase2 <<<1, 128>>>();                                        // 5
    scan_phase3 <<<(NN + 255) / 256, 256>>>();                         // 6
    fill_csr    <<<(NE + 255) / 256, 256>>>(ei, ew);                   // 7

    cudaStreamWaitEvent(0, evJ, 0);

    agg_csr<48, false><<<(NN * 32 + 255) / 256, 256>>>(                // 8
        (const __half*)h1p, (const float*)acc1p, (float*)acc1p);

    gemm_dual<48, 40, true><<<(NN + 63) / 64, dim3(40, 8)>>>(          // 9
        (const float*)acc1p, W2, V2, b2, (__half*)h2p, (float*)acc2p);

    agg_csr<40, true><<<(NN * 32 + 255) / 256, 256>>>(                 // 10
        (const __half*)h2p, (const float*)acc2p, out);
}